// round 9
// baseline (speedup 1.0000x reference)
#include <cuda_runtime.h>
#include <math.h>

#define H 256
#define H2 512
#define VOCAB 8192
#define SEQ 4096

#define CIB 256            // k4 blocks
#define CIR (SEQ / CIB)    // 16 s-rows per block

// ---------------- device scratch (no allocations allowed) ----------------
__device__ float g_Eij[4 * SEQ];     // attention scores, 4 n-quarter partials
__device__ float g_CiP[CIB][H2];     // Ci partials (deterministic reduction)
__device__ float g_Ci[H2];           // context vector
__device__ float g_pre[3 * H];       // gate pre-activations: z, r, h-partial
__device__ float g_logits[VOCAB];

// ---------------- f32x2 packed-math helpers (sm_100+) ----------------
static __device__ __forceinline__ unsigned long long pack2(float lo, float hi) {
    unsigned long long r;
    asm("mov.b64 %0, {%1,%2};" : "=l"(r) : "f"(lo), "f"(hi));
    return r;
}
static __device__ __forceinline__ void unpack2(unsigned long long v, float& lo, float& hi) {
    asm("mov.b64 {%0,%1}, %2;" : "=f"(lo), "=f"(hi) : "l"(v));
}
static __device__ __forceinline__ void fma2(unsigned long long& d,
                                            unsigned long long a,
                                            unsigned long long b) {
    asm("fma.rn.f32x2 %0, %1, %2, %0;" : "+l"(d) : "l"(a), "l"(b));
}

// ---------------- K2: fused attention-score GEMM (wah fused in) ----------
// C[s,n] = enc[s,:] . Ua_w[n,:]
// Eij_part[by][s] = sum_{n in quarter} Va[n]*tanh(C + Wa@h + Wa_b + Ua_b)
#define TM 64
#define TN 64
#define KT 32

__global__ __launch_bounds__(256) void k2_attn(const float* __restrict__ enc,
                                               const float* __restrict__ Ua_w,
                                               const float* __restrict__ Va_w,
                                               const float* __restrict__ Wa_w,
                                               const float* __restrict__ Wa_b,
                                               const float* __restrict__ Ua_b,
                                               const float* __restrict__ hidden) {
    __shared__ __align__(16) unsigned long long As2[TM][KT + 1]; // (a,a) packed
    __shared__ __align__(16) float Bs[KT][TN];
    __shared__ float wah_s[TN];
    __shared__ float vas[TN];
    __shared__ float hs[H];

    int tid = threadIdx.x;
    int s0 = blockIdx.x * TM;
    int n0 = blockIdx.y * TN;

    // stage hidden + Va
    hs[tid] = hidden[tid];
    if (tid < TN) vas[tid] = Va_w[n0 + tid];
    __syncthreads();

    // fused k1: wah_s[r] = Wa@hidden + Wa_b + Ua_b for this block's 64 rows
    {
        int w = tid >> 5, lane = tid & 31;
#pragma unroll
        for (int rr = 0; rr < 8; rr++) {
            int r = w * 8 + rr;              // 0..63
            int g = n0 + r;
            float s = 0.f;
#pragma unroll
            for (int k = 0; k < 8; k++) s += Wa_w[g * H + lane + 32 * k] * hs[lane + 32 * k];
            for (int o = 16; o; o >>= 1) s += __shfl_xor_sync(0xffffffffu, s, o);
            if (lane == 0) wah_s[r] = s + Wa_b[g] + Ua_b[g];
        }
    }

    int tidx = tid & 15;   // n-group (16)
    int tidy = tid >> 4;   // m-group (16)

    unsigned long long acc[4][2];
#pragma unroll
    for (int i = 0; i < 4; i++)
#pragma unroll
        for (int j = 0; j < 2; j++) acc[i][j] = 0ull;

    int ar = tid >> 2, aq = tid & 3;   // A loader: row 0..63, quad 0..3
    int bn = tid >> 2, bq = tid & 3;   // B loader: row 0..63, quad 0..3
    const float4* Abase = reinterpret_cast<const float4*>(enc + (size_t)(s0 + ar) * H2);
    const float4* Bbase = reinterpret_cast<const float4*>(Ua_w + (size_t)(n0 + bn) * H2);

    float4 a0 = Abase[aq], a1 = Abase[aq + 4];
    float4 b0 = Bbase[bq * 2], b1 = Bbase[bq * 2 + 1];
    __syncthreads();  // wah_s ready before main loop writes smem

    const int NIT = H2 / KT;
    for (int it = 0; it < NIT; ++it) {
        // stage registers -> smem
        As2[ar][4 * aq + 0]  = pack2(a0.x, a0.x);
        As2[ar][4 * aq + 1]  = pack2(a0.y, a0.y);
        As2[ar][4 * aq + 2]  = pack2(a0.z, a0.z);
        As2[ar][4 * aq + 3]  = pack2(a0.w, a0.w);
        As2[ar][4 * aq + 16] = pack2(a1.x, a1.x);
        As2[ar][4 * aq + 17] = pack2(a1.y, a1.y);
        As2[ar][4 * aq + 18] = pack2(a1.z, a1.z);
        As2[ar][4 * aq + 19] = pack2(a1.w, a1.w);
        int cb = bq * 8;
        Bs[cb + 0][bn] = b0.x;  Bs[cb + 1][bn] = b0.y;
        Bs[cb + 2][bn] = b0.z;  Bs[cb + 3][bn] = b0.w;
        Bs[cb + 4][bn] = b1.x;  Bs[cb + 5][bn] = b1.y;
        Bs[cb + 6][bn] = b1.z;  Bs[cb + 7][bn] = b1.w;
        __syncthreads();

        if (it + 1 < NIT) {  // prefetch next tile
            int o = (it + 1) * 8;
            a0 = Abase[o + aq];      a1 = Abase[o + aq + 4];
            b0 = Bbase[o + bq * 2];  b1 = Bbase[o + bq * 2 + 1];
        }

#pragma unroll 8
        for (int k = 0; k < KT; k++) {
            unsigned long long a[4], b[2];
#pragma unroll
            for (int i = 0; i < 4; i++) a[i] = As2[tidy * 4 + i][k];
#pragma unroll
            for (int j = 0; j < 2; j++)
                b[j] = *reinterpret_cast<const unsigned long long*>(&Bs[k][tidx * 2 + 32 * j]);
#pragma unroll
            for (int i = 0; i < 4; i++)
#pragma unroll
                for (int j = 0; j < 2; j++) fma2(acc[i][j], a[i], b[j]);
        }
        __syncthreads();
    }

    // fused epilogue: tanh + Va-dot, reduce across the 16 n-thread groups
#pragma unroll
    for (int i = 0; i < 4; i++) {
        float p = 0.f;
#pragma unroll
        for (int j = 0; j < 2; j++) {
            float c0, c1;
            unpack2(acc[i][j], c0, c1);
            int nl = tidx * 2 + 32 * j;
            float e0 = tanhf(c0 + wah_s[nl]);
            float e1 = tanhf(c1 + wah_s[nl + 1]);
            p += e0 * vas[nl] + e1 * vas[nl + 1];
        }
        for (int o = 1; o < 16; o <<= 1) p += __shfl_xor_sync(0xffffffffu, p, o, 16);
        if (tidx == 0) g_Eij[blockIdx.y * SEQ + s0 + tidy * 4 + i] = p;
    }
}

// ---------------- K3: softmax over S (single block) ----------------------
__global__ __launch_bounds__(256) void k3_softmax(float* __restrict__ aij) {
    __shared__ float red[8];
    __shared__ float stat;
    int tid = threadIdx.x;

    float e[16];
    float mx = -1e30f;
#pragma unroll
    for (int i = 0; i < 16; i++) {
        int idx = i * 256 + tid;
        e[i] = g_Eij[idx] + g_Eij[SEQ + idx] + g_Eij[2 * SEQ + idx] + g_Eij[3 * SEQ + idx];
        mx = fmaxf(mx, e[i]);
    }
    for (int o = 16; o; o >>= 1) mx = fmaxf(mx, __shfl_xor_sync(0xffffffffu, mx, o));
    if ((tid & 31) == 0) red[tid >> 5] = mx;
    __syncthreads();
    if (tid == 0) {
        float m = red[0];
        for (int i = 1; i < 8; i++) m = fmaxf(m, red[i]);
        stat = m;
    }
    __syncthreads();
    mx = stat;

    float sum = 0.f;
#pragma unroll
    for (int i = 0; i < 16; i++) { e[i] = expf(e[i] - mx); sum += e[i]; }
    for (int o = 16; o; o >>= 1) sum += __shfl_xor_sync(0xffffffffu, sum, o);
    __syncthreads();
    if ((tid & 31) == 0) red[tid >> 5] = sum;
    __syncthreads();
    if (tid == 0) {
        float t = 0.f;
        for (int i = 0; i < 8; i++) t += red[i];
        stat = t;
    }
    __syncthreads();
    float inv = 1.f / stat;
#pragma unroll
    for (int i = 0; i < 16; i++) aij[i * 256 + tid] = e[i] * inv;
}

// ---------------- K4: Ci partials (256 blocks x 512 thr, deterministic) ---
__global__ __launch_bounds__(512) void k4_ci(const float* __restrict__ enc,
                                             const float* __restrict__ aij) {
    int b = blockIdx.x, tid = threadIdx.x;
    const float* ep = enc + (size_t)b * CIR * H2 + tid;
    const float* ap = aij + b * CIR;
    float w[CIR];
#pragma unroll
    for (int s = 0; s < CIR; s++) w[s] = __ldg(ap + s);
    float acc0 = 0.f, acc1 = 0.f;
#pragma unroll
    for (int s = 0; s < CIR; s += 2) {
        acc0 += w[s] * __ldg(ep + (size_t)s * H2);
        acc1 += w[s + 1] * __ldg(ep + (size_t)(s + 1) * H2);
    }
    g_CiP[b][tid] = acc0 + acc1;
}

// ---------------- K5: reduce Ci partials (4 blocks, fixed order) ----------
__global__ __launch_bounds__(512) void k5_cired() {
    __shared__ float sm[512];
    int tid = threadIdx.x;
    int col = blockIdx.x * 128 + (tid >> 2);
    int seg = tid & 3;
    float s = 0.f;
#pragma unroll 8
    for (int p = seg * 64; p < seg * 64 + 64; p++) s += g_CiP[p][col];
    sm[tid] = s;
    __syncthreads();
    if (seg == 0) g_Ci[col] = sm[tid] + sm[tid + 1] + sm[tid + 2] + sm[tid + 3];
}

// ---------------- K6: gate pre-activations (768 blocks x 512 thr) --------
__global__ __launch_bounds__(512) void k6_gates(
    const float* __restrict__ emb, const int* __restrict__ tokp,
    const float* __restrict__ hidden,
    const float* __restrict__ Uz, const float* __restrict__ Uzb,
    const float* __restrict__ Wz, const float* __restrict__ Wzb,
    const float* __restrict__ Cz, const float* __restrict__ Czb,
    const float* __restrict__ Ur, const float* __restrict__ Urb,
    const float* __restrict__ Wr, const float* __restrict__ Wrb,
    const float* __restrict__ Cr, const float* __restrict__ Crb,
    const float* __restrict__ Uh, const float* __restrict__ Uhb,
    const float* __restrict__ Whb,
    const float* __restrict__ Ch, const float* __restrict__ Chb) {
    __shared__ float red[16];
    int g = blockIdx.x >> 8, row = blockIdx.x & 255, tid = threadIdx.x;
    const float* U = (g == 0) ? Uz : (g == 1) ? Ur : Uh;
    int tok = __ldg(tokp);
    const float4* y4 = reinterpret_cast<const float4*>(emb + (size_t)tok * VOCAB);
    const float4* u4 = reinterpret_cast<const float4*>(U + (size_t)row * VOCAB);

    float s = 0.f;
#pragma unroll
    for (int q = 0; q < 4; q++) {
        int i = tid + q * 512;
        float4 u = u4[i], y = y4[i];
        s += u.x * y.x + u.y * y.y + u.z * y.z + u.w * y.w;
    }
    if (tid < 256) {
        if (g < 2) {
            const float* W = (g == 0) ? Wz : Wr;
            s += W[row * H + tid] * hidden[tid];
        }
        const float* C = (g == 0) ? Cz : (g == 1) ? Cr : Ch;
        s += C[row * H2 + tid] * g_Ci[tid] + C[row * H2 + tid + 256] * g_Ci[tid + 256];
    }

    for (int o = 16; o; o >>= 1) s += __shfl_xor_sync(0xffffffffu, s, o);
    if ((tid & 31) == 0) red[tid >> 5] = s;
    __syncthreads();
    if (tid == 0) {
        float t = 0.f;
#pragma unroll
        for (int i = 0; i < 16; i++) t += red[i];
        float bias = (g == 0) ? (Uzb[row] + Wzb[row] + Czb[row])
                   : (g == 1) ? (Urb[row] + Wrb[row] + Crb[row])
                              : (Uhb[row] + Whb[row] + Chb[row]);
        g_pre[g * H + row] = t + bias;
    }
}

// ---------------- K7: finish GRU -> hidden_new (32 blocks) ----------------
__global__ __launch_bounds__(256) void k7_combine(const float* __restrict__ Wh,
                                                  const float* __restrict__ hidden,
                                                  float* __restrict__ hn_out) {
    __shared__ float rh[H];
    int tid = threadIdx.x;
    float rr = 1.f / (1.f + expf(-g_pre[H + tid]));
    rh[tid] = rr * hidden[tid];
    __syncthreads();
    int w = tid >> 5, lane = tid & 31;
    int row = blockIdx.x * 8 + w;
    float s = 0.f;
    for (int k = lane; k < H; k += 32) s += Wh[row * H + k] * rh[k];
    for (int o = 16; o; o >>= 1) s += __shfl_xor_sync(0xffffffffu, s, o);
    if (lane == 0) {
        float c = tanhf(s + g_pre[2 * H + row]);
        float z = 1.f / (1.f + expf(-g_pre[row]));
        hn_out[row] = (1.f - z) * c + z * hidden[row];
    }
}

// ---------------- K8: logits = V_w @ hidden_new + V_b (1024 blocks) -------
__global__ __launch_bounds__(256) void k8_logits(const float* __restrict__ Vw,
                                                 const float* __restrict__ Vb,
                                                 const float* __restrict__ hn) {
    __shared__ float hs[H];
    int tid = threadIdx.x;
    hs[tid] = hn[tid];
    __syncthreads();
    int w = tid >> 5, lane = tid & 31;
    int row = blockIdx.x * 8 + w;
    const float4* v4 = reinterpret_cast<const float4*>(Vw + (size_t)row * H);
    const float4* h4 = reinterpret_cast<const float4*>(hs);
    float4 a = v4[lane], b = h4[lane];
    float s = a.x * b.x + a.y * b.y + a.z * b.z + a.w * b.w;
    a = v4[lane + 32]; b = h4[lane + 32];
    s += a.x * b.x + a.y * b.y + a.z * b.z + a.w * b.w;
    for (int o = 16; o; o >>= 1) s += __shfl_xor_sync(0xffffffffu, s, o);
    if (lane == 0) g_logits[row] = s + Vb[row];
}

// ---------------- K9: log_softmax over V (single block) -------------------
__global__ __launch_bounds__(1024) void k9_lsm(float* __restrict__ out) {
    __shared__ float red[32];
    __shared__ float stat;
    int tid = threadIdx.x;
    float v[8];
    float mx = -1e30f;
#pragma unroll
    for (int i = 0; i < 8; i++) { v[i] = g_logits[i * 1024 + tid]; mx = fmaxf(mx, v[i]); }
    for (int o = 16; o; o >>= 1) mx = fmaxf(mx, __shfl_xor_sync(0xffffffffu, mx, o));
    if ((tid & 31) == 0) red[tid >> 5] = mx;
    __syncthreads();
    if (tid == 0) {
        float m = red[0];
        for (int i = 1; i < 32; i++) m = fmaxf(m, red[i]);
        stat = m;
    }
    __syncthreads();
    mx = stat;
    float sum = 0.f;
#pragma unroll
    for (int i = 0; i < 8; i++) sum += expf(v[i] - mx);
    for (int o = 16; o; o >>= 1) sum += __shfl_xor_sync(0xffffffffu, sum, o);
    __syncthreads();
    if ((tid & 31) == 0) red[tid >> 5] = sum;
    __syncthreads();
    if (tid == 0) {
        float t = 0.f;
        for (int i = 0; i < 32; i++) t += red[i];
        stat = t;
    }
    __syncthreads();
    float lse = mx + logf(stat);
#pragma unroll
    for (int i = 0; i < 8; i++) out[i * 1024 + tid] = v[i] - lse;
}

// ---------------- launch ----------------
extern "C" void kernel_launch(void* const* d_in, const int* in_sizes, int n_in,
                              void* d_out, int out_size) {
    const int*   input_tok = (const int*)d_in[0];
    const float* hidden    = (const float*)d_in[1];
    const float* enc       = (const float*)d_in[2];
    const float* emb       = (const float*)d_in[3];
    const float* Uz_w = (const float*)d_in[4],  *Uz_b = (const float*)d_in[5];
    const float* Wz_w = (const float*)d_in[6],  *Wz_b = (const float*)d_in[7];
    const float* Cz_w = (const float*)d_in[8],  *Cz_b = (const float*)d_in[9];
    const float* Ur_w = (const float*)d_in[10], *Ur_b = (const float*)d_in[11];
    const float* Wr_w = (const float*)d_in[12], *Wr_b = (const float*)d_in[13];
    const float* Cr_w = (const float*)d_in[14], *Cr_b = (const float*)d_in[15];
    const float* Uh_w = (const float*)d_in[16], *Uh_b = (const float*)d_in[17];
    const float* Wh_w = (const float*)d_in[18], *Wh_b = (const float*)d_in[19];
    const float* Ch_w = (const float*)d_in[20], *Ch_b = (const float*)d_in[21];
    const float* Ua_w = (const float*)d_in[22], *Ua_b = (const float*)d_in[23];
    const float* Wa_w = (const float*)d_in[24], *Wa_b = (const float*)d_in[25];
    const float* Va_w = (const float*)d_in[26], *Va_b = (const float*)d_in[27];
    const float* V_w  = (const float*)d_in[28], *V_b  = (const float*)d_in[29];
    (void)Va_b; (void)in_sizes; (void)n_in; (void)out_size;

    float* out = (float*)d_out;           // [0:8192) log-probs
    float* hn  = out + VOCAB;             // [8192:8448) hidden_new
    float* aij = out + VOCAB + H;         // [8448:12544) attention weights

    k2_attn<<<dim3(SEQ / TM, 4), 256>>>(enc, Ua_w, Va_w, Wa_w, Wa_b, Ua_b, hidden);
    k3_softmax<<<1, 256>>>(aij);
    k4_ci<<<CIB, 512>>>(enc, aij);
    k5_cired<<<4, 512>>>();
    k6_gates<<<768, 512>>>(emb, input_tok, hidden,
                           Uz_w, Uz_b, Wz_w, Wz_b, Cz_w, Cz_b,
                           Ur_w, Ur_b, Wr_w, Wr_b, Cr_w, Cr_b,
                           Uh_w, Uh_b, Wh_b, Ch_w, Ch_b);
    k7_combine<<<32, 256>>>(Wh_w, hidden, hn);
    k8_logits<<<VOCAB / 8, 256>>>(V_w, V_b, hn);
    k9_lsm<<<1, 1024>>>(out);
}

// round 11
// speedup vs baseline: 1.0265x; 1.0265x over previous
#include <cuda_runtime.h>
#include <math.h>

#define H 256
#define H2 512
#define VOCAB 8192
#define SEQ 4096

#define CIB 128            // k4 blocks
#define CIR (SEQ / CIB)    // 32 s-rows per block

// ---------------- device scratch (no allocations allowed) ----------------
__device__ float g_Eij[4 * SEQ];     // attention scores, 4 n-quarter partials
__device__ float g_CiP[CIB][H2];     // Ci partials (deterministic reduction)
__device__ float g_Ci[H2];           // context vector
__device__ float g_pre[3 * H];       // gate pre-activations: z, r, h-partial
__device__ float g_logits[VOCAB];

// ---------------- f32x2 packed-math helpers (sm_100+) ----------------
static __device__ __forceinline__ unsigned long long pack2(float lo, float hi) {
    unsigned long long r;
    asm("mov.b64 %0, {%1,%2};" : "=l"(r) : "f"(lo), "f"(hi));
    return r;
}
static __device__ __forceinline__ void unpack2(unsigned long long v, float& lo, float& hi) {
    asm("mov.b64 {%0,%1}, %2;" : "=f"(lo), "=f"(hi) : "l"(v));
}
static __device__ __forceinline__ void fma2(unsigned long long& d,
                                            unsigned long long a,
                                            unsigned long long b) {
    asm("fma.rn.f32x2 %0, %1, %2, %0;" : "+l"(d) : "l"(a), "l"(b));
}

// ---------------- K2: fused attention-score GEMM (wah fused in) ----------
// C[s,n] = enc[s,:] . Ua_w[n,:]
// Eij_part[by][s] = sum_{n in quarter} Va[n]*tanh(C + Wa@h + Wa_b + Ua_b)
#define TM 64
#define TN 64
#define KT 32

__global__ __launch_bounds__(256) void k2_attn(const float* __restrict__ enc,
                                               const float* __restrict__ Ua_w,
                                               const float* __restrict__ Va_w,
                                               const float* __restrict__ Wa_w,
                                               const float* __restrict__ Wa_b,
                                               const float* __restrict__ Ua_b,
                                               const float* __restrict__ hidden) {
    __shared__ __align__(16) unsigned long long As2[TM][KT + 1]; // (a,a) packed
    __shared__ __align__(16) float Bs[KT][TN];
    __shared__ float wah_s[TN];
    __shared__ float vas[TN];
    __shared__ float hs[H];

    int tid = threadIdx.x;
    int s0 = blockIdx.x * TM;
    int n0 = blockIdx.y * TN;

    // stage hidden + Va
    hs[tid] = hidden[tid];
    if (tid < TN) vas[tid] = Va_w[n0 + tid];
    __syncthreads();

    // fused k1: wah_s[r] = Wa@hidden + Wa_b + Ua_b for this block's 64 rows
    {
        int w = tid >> 5, lane = tid & 31;
#pragma unroll
        for (int rr = 0; rr < 8; rr++) {
            int r = w * 8 + rr;              // 0..63
            int g = n0 + r;
            float s = 0.f;
#pragma unroll
            for (int k = 0; k < 8; k++) s += Wa_w[g * H + lane + 32 * k] * hs[lane + 32 * k];
            for (int o = 16; o; o >>= 1) s += __shfl_xor_sync(0xffffffffu, s, o);
            if (lane == 0) wah_s[r] = s + Wa_b[g] + Ua_b[g];
        }
    }

    int tidx = tid & 15;   // n-group (16)
    int tidy = tid >> 4;   // m-group (16)

    unsigned long long acc[4][2];
#pragma unroll
    for (int i = 0; i < 4; i++)
#pragma unroll
        for (int j = 0; j < 2; j++) acc[i][j] = 0ull;

    int ar = tid >> 2, aq = tid & 3;   // A loader: row 0..63, quad 0..3
    int bn = tid >> 2, bq = tid & 3;   // B loader: row 0..63, quad 0..3
    const float4* Abase = reinterpret_cast<const float4*>(enc + (size_t)(s0 + ar) * H2);
    const float4* Bbase = reinterpret_cast<const float4*>(Ua_w + (size_t)(n0 + bn) * H2);

    float4 a0 = Abase[aq], a1 = Abase[aq + 4];
    float4 b0 = Bbase[bq * 2], b1 = Bbase[bq * 2 + 1];
    __syncthreads();  // wah_s ready before main loop writes smem

    const int NIT = H2 / KT;
    for (int it = 0; it < NIT; ++it) {
        // stage registers -> smem
        As2[ar][4 * aq + 0]  = pack2(a0.x, a0.x);
        As2[ar][4 * aq + 1]  = pack2(a0.y, a0.y);
        As2[ar][4 * aq + 2]  = pack2(a0.z, a0.z);
        As2[ar][4 * aq + 3]  = pack2(a0.w, a0.w);
        As2[ar][4 * aq + 16] = pack2(a1.x, a1.x);
        As2[ar][4 * aq + 17] = pack2(a1.y, a1.y);
        As2[ar][4 * aq + 18] = pack2(a1.z, a1.z);
        As2[ar][4 * aq + 19] = pack2(a1.w, a1.w);
        int cb = bq * 8;
        Bs[cb + 0][bn] = b0.x;  Bs[cb + 1][bn] = b0.y;
        Bs[cb + 2][bn] = b0.z;  Bs[cb + 3][bn] = b0.w;
        Bs[cb + 4][bn] = b1.x;  Bs[cb + 5][bn] = b1.y;
        Bs[cb + 6][bn] = b1.z;  Bs[cb + 7][bn] = b1.w;
        __syncthreads();

        if (it + 1 < NIT) {  // prefetch next tile
            int o = (it + 1) * 8;
            a0 = Abase[o + aq];      a1 = Abase[o + aq + 4];
            b0 = Bbase[o + bq * 2];  b1 = Bbase[o + bq * 2 + 1];
        }

#pragma unroll 8
        for (int k = 0; k < KT; k++) {
            unsigned long long a[4], b[2];
#pragma unroll
            for (int i = 0; i < 4; i++) a[i] = As2[tidy * 4 + i][k];
#pragma unroll
            for (int j = 0; j < 2; j++)
                b[j] = *reinterpret_cast<const unsigned long long*>(&Bs[k][tidx * 2 + 32 * j]);
#pragma unroll
            for (int i = 0; i < 4; i++)
#pragma unroll
                for (int j = 0; j < 2; j++) fma2(acc[i][j], a[i], b[j]);
        }
        __syncthreads();
    }

    // fused epilogue: tanh + Va-dot, reduce across the 16 n-thread groups
#pragma unroll
    for (int i = 0; i < 4; i++) {
        float p = 0.f;
#pragma unroll
        for (int j = 0; j < 2; j++) {
            float c0, c1;
            unpack2(acc[i][j], c0, c1);
            int nl = tidx * 2 + 32 * j;
            float e0 = tanhf(c0 + wah_s[nl]);
            float e1 = tanhf(c1 + wah_s[nl + 1]);
            p += e0 * vas[nl] + e1 * vas[nl + 1];
        }
        for (int o = 1; o < 16; o <<= 1) p += __shfl_xor_sync(0xffffffffu, p, o, 16);
        if (tidx == 0) g_Eij[blockIdx.y * SEQ + s0 + tidy * 4 + i] = p;
    }
}

// ---------------- K3: softmax over S (single block) ----------------------
__global__ __launch_bounds__(256) void k3_softmax(float* __restrict__ aij) {
    __shared__ float red[8];
    __shared__ float stat;
    int tid = threadIdx.x;

    float e[16];
    float mx = -1e30f;
#pragma unroll
    for (int i = 0; i < 16; i++) {
        int idx = i * 256 + tid;
        e[i] = g_Eij[idx] + g_Eij[SEQ + idx] + g_Eij[2 * SEQ + idx] + g_Eij[3 * SEQ + idx];
        mx = fmaxf(mx, e[i]);
    }
    for (int o = 16; o; o >>= 1) mx = fmaxf(mx, __shfl_xor_sync(0xffffffffu, mx, o));
    if ((tid & 31) == 0) red[tid >> 5] = mx;
    __syncthreads();
    if (tid == 0) {
        float m = red[0];
        for (int i = 1; i < 8; i++) m = fmaxf(m, red[i]);
        stat = m;
    }
    __syncthreads();
    mx = stat;

    float sum = 0.f;
#pragma unroll
    for (int i = 0; i < 16; i++) { e[i] = expf(e[i] - mx); sum += e[i]; }
    for (int o = 16; o; o >>= 1) sum += __shfl_xor_sync(0xffffffffu, sum, o);
    __syncthreads();
    if ((tid & 31) == 0) red[tid >> 5] = sum;
    __syncthreads();
    if (tid == 0) {
        float t = 0.f;
        for (int i = 0; i < 8; i++) t += red[i];
        stat = t;
    }
    __syncthreads();
    float inv = 1.f / stat;
#pragma unroll
    for (int i = 0; i < 16; i++) aij[i * 256 + tid] = e[i] * inv;
}

// ---------------- K4: Ci partials (128 blocks x 512 thr, deterministic) ---
__global__ __launch_bounds__(512) void k4_ci(const float* __restrict__ enc,
                                             const float* __restrict__ aij) {
    int b = blockIdx.x, tid = threadIdx.x;
    const float* ep = enc + (size_t)b * CIR * H2 + tid;
    const float* ap = aij + b * CIR;
    float w[CIR];
#pragma unroll
    for (int s = 0; s < CIR; s++) w[s] = __ldg(ap + s);
    float acc0 = 0.f, acc1 = 0.f;
#pragma unroll
    for (int s = 0; s < CIR; s += 2) {
        acc0 += w[s] * __ldg(ep + (size_t)s * H2);
        acc1 += w[s + 1] * __ldg(ep + (size_t)(s + 1) * H2);
    }
    g_CiP[b][tid] = acc0 + acc1;
}

// ---------------- K5: reduce Ci partials (8 blocks, coalesced) ------------
// Thread = (seg 0..7, col 0..63). Each thread sums 16 consecutive rows of its
// column: within a warp, 32 consecutive cols -> fully coalesced 128B lines.
__global__ __launch_bounds__(512) void k5_cired() {
    __shared__ float sm[8][64];
    int tid = threadIdx.x;
    int cl = tid & 63;                 // column within this block's 64
    int seg = tid >> 6;                // 0..7 row-segment
    int col = blockIdx.x * 64 + cl;
    float s = 0.f;
#pragma unroll
    for (int r = 0; r < CIB / 8; r++) s += g_CiP[seg * (CIB / 8) + r][col];
    sm[seg][cl] = s;
    __syncthreads();
    if (seg == 0) {
        float t = 0.f;
#pragma unroll
        for (int i = 0; i < 8; i++) t += sm[i][cl];
        g_Ci[col] = t;
    }
}

// ---------------- K6: gate pre-activations (768 blocks x 512 thr) --------
__global__ __launch_bounds__(512) void k6_gates(
    const float* __restrict__ emb, const int* __restrict__ tokp,
    const float* __restrict__ hidden,
    const float* __restrict__ Uz, const float* __restrict__ Uzb,
    const float* __restrict__ Wz, const float* __restrict__ Wzb,
    const float* __restrict__ Cz, const float* __restrict__ Czb,
    const float* __restrict__ Ur, const float* __restrict__ Urb,
    const float* __restrict__ Wr, const float* __restrict__ Wrb,
    const float* __restrict__ Cr, const float* __restrict__ Crb,
    const float* __restrict__ Uh, const float* __restrict__ Uhb,
    const float* __restrict__ Whb,
    const float* __restrict__ Ch, const float* __restrict__ Chb) {
    __shared__ float red[16];
    int g = blockIdx.x >> 8, row = blockIdx.x & 255, tid = threadIdx.x;
    const float* U = (g == 0) ? Uz : (g == 1) ? Ur : Uh;
    int tok = __ldg(tokp);
    const float4* y4 = reinterpret_cast<const float4*>(emb + (size_t)tok * VOCAB);
    const float4* u4 = reinterpret_cast<const float4*>(U + (size_t)row * VOCAB);

    float s = 0.f;
#pragma unroll
    for (int q = 0; q < 4; q++) {
        int i = tid + q * 512;
        float4 u = u4[i], y = y4[i];
        s += u.x * y.x + u.y * y.y + u.z * y.z + u.w * y.w;
    }
    if (tid < 256) {
        if (g < 2) {
            const float* W = (g == 0) ? Wz : Wr;
            s += W[row * H + tid] * hidden[tid];
        }
        const float* C = (g == 0) ? Cz : (g == 1) ? Cr : Ch;
        s += C[row * H2 + tid] * g_Ci[tid] + C[row * H2 + tid + 256] * g_Ci[tid + 256];
    }

    for (int o = 16; o; o >>= 1) s += __shfl_xor_sync(0xffffffffu, s, o);
    if ((tid & 31) == 0) red[tid >> 5] = s;
    __syncthreads();
    if (tid == 0) {
        float t = 0.f;
#pragma unroll
        for (int i = 0; i < 16; i++) t += red[i];
        float bias = (g == 0) ? (Uzb[row] + Wzb[row] + Czb[row])
                   : (g == 1) ? (Urb[row] + Wrb[row] + Crb[row])
                              : (Uhb[row] + Whb[row] + Chb[row]);
        g_pre[g * H + row] = t + bias;
    }
}

// ---------------- K7: finish GRU -> hidden_new (32 blocks) ----------------
__global__ __launch_bounds__(256) void k7_combine(const float* __restrict__ Wh,
                                                  const float* __restrict__ hidden,
                                                  float* __restrict__ hn_out) {
    __shared__ float rh[H];
    int tid = threadIdx.x;
    float rr = 1.f / (1.f + expf(-g_pre[H + tid]));
    rh[tid] = rr * hidden[tid];
    __syncthreads();
    int w = tid >> 5, lane = tid & 31;
    int row = blockIdx.x * 8 + w;
    float s = 0.f;
    for (int k = lane; k < H; k += 32) s += Wh[row * H + k] * rh[k];
    for (int o = 16; o; o >>= 1) s += __shfl_xor_sync(0xffffffffu, s, o);
    if (lane == 0) {
        float c = tanhf(s + g_pre[2 * H + row]);
        float z = 1.f / (1.f + expf(-g_pre[row]));
        hn_out[row] = (1.f - z) * c + z * hidden[row];
    }
}

// ---------------- K8: logits = V_w @ hidden_new + V_b (1024 blocks) -------
__global__ __launch_bounds__(256) void k8_logits(const float* __restrict__ Vw,
                                                 const float* __restrict__ Vb,
                                                 const float* __restrict__ hn) {
    __shared__ float hs[H];
    int tid = threadIdx.x;
    hs[tid] = hn[tid];
    __syncthreads();
    int w = tid >> 5, lane = tid & 31;
    int row = blockIdx.x * 8 + w;
    const float4* v4 = reinterpret_cast<const float4*>(Vw + (size_t)row * H);
    const float4* h4 = reinterpret_cast<const float4*>(hs);
    float4 a = v4[lane], b = h4[lane];
    float s = a.x * b.x + a.y * b.y + a.z * b.z + a.w * b.w;
    a = v4[lane + 32]; b = h4[lane + 32];
    s += a.x * b.x + a.y * b.y + a.z * b.z + a.w * b.w;
    for (int o = 16; o; o >>= 1) s += __shfl_xor_sync(0xffffffffu, s, o);
    if (lane == 0) g_logits[row] = s + Vb[row];
}

// ---------------- K9: log_softmax over V (single block) -------------------
__global__ __launch_bounds__(1024) void k9_lsm(float* __restrict__ out) {
    __shared__ float red[32];
    __shared__ float stat;
    int tid = threadIdx.x;
    float v[8];
    float mx = -1e30f;
#pragma unroll
    for (int i = 0; i < 8; i++) { v[i] = g_logits[i * 1024 + tid]; mx = fmaxf(mx, v[i]); }
    for (int o = 16; o; o >>= 1) mx = fmaxf(mx, __shfl_xor_sync(0xffffffffu, mx, o));
    if ((tid & 31) == 0) red[tid >> 5] = mx;
    __syncthreads();
    if (tid == 0) {
        float m = red[0];
        for (int i = 1; i < 32; i++) m = fmaxf(m, red[i]);
        stat = m;
    }
    __syncthreads();
    mx = stat;
    float sum = 0.f;
#pragma unroll
    for (int i = 0; i < 8; i++) sum += expf(v[i] - mx);
    for (int o = 16; o; o >>= 1) sum += __shfl_xor_sync(0xffffffffu, sum, o);
    __syncthreads();
    if ((tid & 31) == 0) red[tid >> 5] = sum;
    __syncthreads();
    if (tid == 0) {
        float t = 0.f;
        for (int i = 0; i < 32; i++) t += red[i];
        stat = t;
    }
    __syncthreads();
    float lse = mx + logf(stat);
#pragma unroll
    for (int i = 0; i < 8; i++) out[i * 1024 + tid] = v[i] - lse;
}

// ---------------- launch ----------------
extern "C" void kernel_launch(void* const* d_in, const int* in_sizes, int n_in,
                              void* d_out, int out_size) {
    const int*   input_tok = (const int*)d_in[0];
    const float* hidden    = (const float*)d_in[1];
    const float* enc       = (const float*)d_in[2];
    const float* emb       = (const float*)d_in[3];
    const float* Uz_w = (const float*)d_in[4],  *Uz_b = (const float*)d_in[5];
    const float* Wz_w = (const float*)d_in[6],  *Wz_b = (const float*)d_in[7];
    const float* Cz_w = (const float*)d_in[8],  *Cz_b = (const float*)d_in[9];
    const float* Ur_w = (const float*)d_in[10], *Ur_b = (const float*)d_in[11];
    const float* Wr_w = (const float*)d_in[12], *Wr_b = (const float*)d_in[13];
    const float* Cr_w = (const float*)d_in[14], *Cr_b = (const float*)d_in[15];
    const float* Uh_w = (const float*)d_in[16], *Uh_b = (const float*)d_in[17];
    const float* Wh_w = (const float*)d_in[18], *Wh_b = (const float*)d_in[19];
    const float* Ch_w = (const float*)d_in[20], *Ch_b = (const float*)d_in[21];
    const float* Ua_w = (const float*)d_in[22], *Ua_b = (const float*)d_in[23];
    const float* Wa_w = (const float*)d_in[24], *Wa_b = (const float*)d_in[25];
    const float* Va_w = (const float*)d_in[26], *Va_b = (const float*)d_in[27];
    const float* V_w  = (const float*)d_in[28], *V_b  = (const float*)d_in[29];
    (void)Va_b; (void)in_sizes; (void)n_in; (void)out_size;

    float* out = (float*)d_out;           // [0:8192) log-probs
    float* hn  = out + VOCAB;             // [8192:8448) hidden_new
    float* aij = out + VOCAB + H;         // [8448:12544) attention weights

    k2_attn<<<dim3(SEQ / TM, 4), 256>>>(enc, Ua_w, Va_w, Wa_w, Wa_b, Ua_b, hidden);
    k3_softmax<<<1, 256>>>(aij);
    k4_ci<<<CIB, 512>>>(enc, aij);
    k5_cired<<<8, 512>>>();
    k6_gates<<<768, 512>>>(emb, input_tok, hidden,
                           Uz_w, Uz_b, Wz_w, Wz_b, Cz_w, Cz_b,
                           Ur_w, Ur_b, Wr_w, Wr_b, Cr_w, Cr_b,
                           Uh_w, Uh_b, Wh_b, Ch_w, Ch_b);
    k7_combine<<<32, 256>>>(Wh_w, hidden, hn);
    k8_logits<<<VOCAB / 8, 256>>>(V_w, V_b, hn);
    k9_lsm<<<1, 1024>>>(out);
}

// round 14
// speedup vs baseline: 1.0902x; 1.0620x over previous
#include <cuda_runtime.h>
#include <math.h>

#define H 256
#define H2 512
#define VOCAB 8192
#define SEQ 4096
#define NQ 2               // n-quarter partial count for Eij

#define CIB 128            // k4 blocks
#define CIR (SEQ / CIB)    // 32 s-rows per block

// ---------------- device scratch (no allocations allowed) ----------------
__device__ float g_Eij[NQ * SEQ];    // attention scores, NQ n-half partials
__device__ float g_CiP[CIB][H2];     // Ci partials (deterministic reduction)
__device__ float g_Ci[H2];           // context vector
__device__ float g_pre[3 * H];       // gate pre-activations: z, r, h-partial
__device__ float g_logits[VOCAB];

// ---------------- f32x2 packed-math helpers (sm_100+) ----------------
static __device__ __forceinline__ unsigned long long pack2(float lo, float hi) {
    unsigned long long r;
    asm("mov.b64 %0, {%1,%2};" : "=l"(r) : "f"(lo), "f"(hi));
    return r;
}
static __device__ __forceinline__ void unpack2(unsigned long long v, float& lo, float& hi) {
    asm("mov.b64 {%0,%1}, %2;" : "=f"(lo), "=f"(hi) : "l"(v));
}
static __device__ __forceinline__ void fma2(unsigned long long& d,
                                            unsigned long long a,
                                            unsigned long long b) {
    asm("fma.rn.f32x2 %0, %1, %2, %0;" : "+l"(d) : "l"(a), "l"(b));
}

// ---------------- K2: fused attention-score GEMM ----------------
// C[s,n] = enc[s,:] . Ua_w[n,:]
// Eij_part[by][s] = sum_{n in half} Va[n]*tanh(C + Wa@h + Wa_b + Ua_b)
//
// 128 threads, TM=64 (s), TN=128 (n), KT=32.
// Thread tile 8m x 8n (32 f32x2 accs). A stored PLAIN in smem; a-pairs are
// built with register movs (alu pipe) so smem traffic is 64 B/thread/k for
// 32 FFMA2 = 2 B/fma2 -> crossbar (128 B/cyc) exactly matches FFMA2 issue.
#define TM 64
#define TN 128
#define KT 32

__global__ __launch_bounds__(128) void k2_attn(const float* __restrict__ enc,
                                               const float* __restrict__ Ua_w,
                                               const float* __restrict__ Va_w,
                                               const float* __restrict__ Wa_w,
                                               const float* __restrict__ Wa_b,
                                               const float* __restrict__ Ua_b,
                                               const float* __restrict__ hidden) {
    __shared__ __align__(16) float As[KT][TM];   // 8 KB, plain floats
    __shared__ __align__(16) float Bs[KT][TN];   // 16 KB
    __shared__ float wah_s[TN];
    __shared__ float vas[TN];
    __shared__ __align__(16) float hs[H];

    int tid = threadIdx.x;
    int s0 = blockIdx.x * TM;
    int n0 = blockIdx.y * TN;

    // stage hidden + Va
    hs[tid] = hidden[tid];
    hs[tid + 128] = hidden[tid + 128];
    vas[tid] = Va_w[n0 + tid];

    // staging pointers + prefetch tile 0 (issued before wah compute so the
    // GMEM latency overlaps the wah dot products)
    int ar = tid >> 1, ac = tid & 1;   // A: row 0..63, k-half 0..1
    const float4* Ab = reinterpret_cast<const float4*>(enc + (size_t)(s0 + ar) * H2);
    const float4* Bb = reinterpret_cast<const float4*>(Ua_w + (size_t)(n0 + tid) * H2);
    float4 pa[4], pb[8];
#pragma unroll
    for (int q = 0; q < 4; q++) pa[q] = Ab[ac * 4 + q];
#pragma unroll
    for (int q = 0; q < 8; q++) pb[q] = Bb[q];

    __syncthreads();   // hs ready

    // fused k1: wah_s[tid] = Wa_w[n0+tid] . hidden + Wa_b + Ua_b  (one row/thread)
    {
        int g = n0 + tid;
        const float4* w4 = reinterpret_cast<const float4*>(Wa_w + (size_t)g * H);
        const float4* h4 = reinterpret_cast<const float4*>(hs);
        float r0 = 0.f, r1 = 0.f, r2 = 0.f, r3 = 0.f;
#pragma unroll
        for (int q = 0; q < 64; q += 4) {
            float4 w0 = w4[q + 0], h0 = h4[q + 0];
            float4 w1 = w4[q + 1], h1 = h4[q + 1];
            float4 w2 = w4[q + 2], h2 = h4[q + 2];
            float4 w3 = w4[q + 3], h3 = h4[q + 3];
            r0 += w0.x * h0.x + w0.y * h0.y + w0.z * h0.z + w0.w * h0.w;
            r1 += w1.x * h1.x + w1.y * h1.y + w1.z * h1.z + w1.w * h1.w;
            r2 += w2.x * h2.x + w2.y * h2.y + w2.z * h2.z + w2.w * h2.w;
            r3 += w3.x * h3.x + w3.y * h3.y + w3.z * h3.z + w3.w * h3.w;
        }
        wah_s[tid] = (r0 + r1) + (r2 + r3) + Wa_b[g] + Ua_b[g];
    }

    int tidx = tid & 15;   // n-group: n = tidx*8 + 0..7
    int tidy = tid >> 4;   // m-group: m = tidy*8 + 0..7  (tidy 0..7)

    unsigned long long acc[8][4];
#pragma unroll
    for (int i = 0; i < 8; i++)
#pragma unroll
        for (int j = 0; j < 4; j++) acc[i][j] = 0ull;

    const int NIT = H2 / KT;   // 16
    for (int it = 0; it < NIT; ++it) {
        // stage registers -> smem (transposed to k-major)
#pragma unroll
        for (int q = 0; q < 4; q++) {
            As[ac * 16 + q * 4 + 0][ar] = pa[q].x;
            As[ac * 16 + q * 4 + 1][ar] = pa[q].y;
            As[ac * 16 + q * 4 + 2][ar] = pa[q].z;
            As[ac * 16 + q * 4 + 3][ar] = pa[q].w;
        }
#pragma unroll
        for (int q = 0; q < 8; q++) {
            Bs[q * 4 + 0][tid] = pb[q].x;
            Bs[q * 4 + 1][tid] = pb[q].y;
            Bs[q * 4 + 2][tid] = pb[q].z;
            Bs[q * 4 + 3][tid] = pb[q].w;
        }
        __syncthreads();

        if (it + 1 < NIT) {   // prefetch next tile
            int o = (it + 1) * 8;
#pragma unroll
            for (int q = 0; q < 4; q++) pa[q] = Ab[o + ac * 4 + q];
#pragma unroll
            for (int q = 0; q < 8; q++) pb[q] = Bb[o + q];
        }

#pragma unroll 8
        for (int k = 0; k < KT; k++) {
            float4 af0 = *reinterpret_cast<const float4*>(&As[k][tidy * 8]);
            float4 af1 = *reinterpret_cast<const float4*>(&As[k][tidy * 8 + 4]);
            ulonglong2 b01 = *reinterpret_cast<const ulonglong2*>(&Bs[k][tidx * 8]);
            ulonglong2 b23 = *reinterpret_cast<const ulonglong2*>(&Bs[k][tidx * 8 + 4]);
            unsigned long long a[8], b[4];
            a[0] = pack2(af0.x, af0.x);  a[1] = pack2(af0.y, af0.y);
            a[2] = pack2(af0.z, af0.z);  a[3] = pack2(af0.w, af0.w);
            a[4] = pack2(af1.x, af1.x);  a[5] = pack2(af1.y, af1.y);
            a[6] = pack2(af1.z, af1.z);  a[7] = pack2(af1.w, af1.w);
            b[0] = b01.x; b[1] = b01.y; b[2] = b23.x; b[3] = b23.y;
#pragma unroll
            for (int i = 0; i < 8; i++)
#pragma unroll
                for (int j = 0; j < 4; j++) fma2(acc[i][j], a[i], b[j]);
        }
        __syncthreads();
    }

    // fused epilogue: tanh + Va-dot, reduce over the 16 tidx groups (width 16)
#pragma unroll
    for (int i = 0; i < 8; i++) {
        float p = 0.f;
#pragma unroll
        for (int j = 0; j < 4; j++) {
            float c0, c1;
            unpack2(acc[i][j], c0, c1);
            int nl = tidx * 8 + 2 * j;
            float e0 = tanhf(c0 + wah_s[nl]);
            float e1 = tanhf(c1 + wah_s[nl + 1]);
            p += e0 * vas[nl] + e1 * vas[nl + 1];
        }
        for (int o = 1; o < 16; o <<= 1) p += __shfl_xor_sync(0xffffffffu, p, o, 16);
        if (tidx == 0) g_Eij[blockIdx.y * SEQ + s0 + tidy * 8 + i] = p;
    }
}

// ---------------- K3: softmax over S (single block) ----------------------
__global__ __launch_bounds__(256) void k3_softmax(float* __restrict__ aij) {
    __shared__ float red[8];
    __shared__ float stat;
    int tid = threadIdx.x;

    float e[16];
    float mx = -1e30f;
#pragma unroll
    for (int i = 0; i < 16; i++) {
        int idx = i * 256 + tid;
        e[i] = g_Eij[idx] + g_Eij[SEQ + idx];
        mx = fmaxf(mx, e[i]);
    }
    for (int o = 16; o; o >>= 1) mx = fmaxf(mx, __shfl_xor_sync(0xffffffffu, mx, o));
    if ((tid & 31) == 0) red[tid >> 5] = mx;
    __syncthreads();
    if (tid == 0) {
        float m = red[0];
        for (int i = 1; i < 8; i++) m = fmaxf(m, red[i]);
        stat = m;
    }
    __syncthreads();
    mx = stat;

    float sum = 0.f;
#pragma unroll
    for (int i = 0; i < 16; i++) { e[i] = expf(e[i] - mx); sum += e[i]; }
    for (int o = 16; o; o >>= 1) sum += __shfl_xor_sync(0xffffffffu, sum, o);
    __syncthreads();
    if ((tid & 31) == 0) red[tid >> 5] = sum;
    __syncthreads();
    if (tid == 0) {
        float t = 0.f;
        for (int i = 0; i < 8; i++) t += red[i];
        stat = t;
    }
    __syncthreads();
    float inv = 1.f / stat;
#pragma unroll
    for (int i = 0; i < 16; i++) aij[i * 256 + tid] = e[i] * inv;
}

// ---------------- K4: Ci partials (128 blocks x 512 thr, deterministic) ---
__global__ __launch_bounds__(512) void k4_ci(const float* __restrict__ enc,
                                             const float* __restrict__ aij) {
    int b = blockIdx.x, tid = threadIdx.x;
    const float* ep = enc + (size_t)b * CIR * H2 + tid;
    const float* ap = aij + b * CIR;
    float w[CIR];
#pragma unroll
    for (int s = 0; s < CIR; s++) w[s] = __ldg(ap + s);
    float acc0 = 0.f, acc1 = 0.f;
#pragma unroll
    for (int s = 0; s < CIR; s += 2) {
        acc0 += w[s] * __ldg(ep + (size_t)s * H2);
        acc1 += w[s + 1] * __ldg(ep + (size_t)(s + 1) * H2);
    }
    g_CiP[b][tid] = acc0 + acc1;
}

// ---------------- K5: reduce Ci partials (8 blocks, coalesced) ------------
__global__ __launch_bounds__(512) void k5_cired() {
    __shared__ float sm[8][64];
    int tid = threadIdx.x;
    int cl = tid & 63;                 // column within this block's 64
    int seg = tid >> 6;                // 0..7 row-segment
    int col = blockIdx.x * 64 + cl;
    float s = 0.f;
#pragma unroll
    for (int r = 0; r < CIB / 8; r++) s += g_CiP[seg * (CIB / 8) + r][col];
    sm[seg][cl] = s;
    __syncthreads();
    if (seg == 0) {
        float t = 0.f;
#pragma unroll
        for (int i = 0; i < 8; i++) t += sm[i][cl];
        g_Ci[col] = t;
    }
}

// ---------------- K6: gate pre-activations (768 blocks x 512 thr) --------
__global__ __launch_bounds__(512) void k6_gates(
    const float* __restrict__ emb, const int* __restrict__ tokp,
    const float* __restrict__ hidden,
    const float* __restrict__ Uz, const float* __restrict__ Uzb,
    const float* __restrict__ Wz, const float* __restrict__ Wzb,
    const float* __restrict__ Cz, const float* __restrict__ Czb,
    const float* __restrict__ Ur, const float* __restrict__ Urb,
    const float* __restrict__ Wr, const float* __restrict__ Wrb,
    const float* __restrict__ Cr, const float* __restrict__ Crb,
    const float* __restrict__ Uh, const float* __restrict__ Uhb,
    const float* __restrict__ Whb,
    const float* __restrict__ Ch, const float* __restrict__ Chb) {
    __shared__ float red[16];
    int g = blockIdx.x >> 8, row = blockIdx.x & 255, tid = threadIdx.x;
    const float* U = (g == 0) ? Uz : (g == 1) ? Ur : Uh;
    int tok = __ldg(tokp);
    const float4* y4 = reinterpret_cast<const float4*>(emb + (size_t)tok * VOCAB);
    const float4* u4 = reinterpret_cast<const float4*>(U + (size_t)row * VOCAB);

    float s = 0.f;
#pragma unroll
    for (int q = 0; q < 4; q++) {
        int i = tid + q * 512;
        float4 u = u4[i], y = y4[i];
        s += u.x * y.x + u.y * y.y + u.z * y.z + u.w * y.w;
    }
    if (tid < 256) {
        if (g < 2) {
            const float* W = (g == 0) ? Wz : Wr;
            s += W[row * H + tid] * hidden[tid];
        }
        const float* C = (g == 0) ? Cz : (g == 1) ? Cr : Ch;
        s += C[row * H2 + tid] * g_Ci[tid] + C[row * H2 + tid + 256] * g_Ci[tid + 256];
    }

    for (int o = 16; o; o >>= 1) s += __shfl_xor_sync(0xffffffffu, s, o);
    if ((tid & 31) == 0) red[tid >> 5] = s;
    __syncthreads();
    if (tid == 0) {
        float t = 0.f;
#pragma unroll
        for (int i = 0; i < 16; i++) t += red[i];
        float bias = (g == 0) ? (Uzb[row] + Wzb[row] + Czb[row])
                   : (g == 1) ? (Urb[row] + Wrb[row] + Crb[row])
                              : (Uhb[row] + Whb[row] + Chb[row]);
        g_pre[g * H + row] = t + bias;
    }
}

// ---------------- K7: finish GRU -> hidden_new (32 blocks) ----------------
__global__ __launch_bounds__(256) void k7_combine(const float* __restrict__ Wh,
                                                  const float* __restrict__ hidden,
                                                  float* __restrict__ hn_out) {
    __shared__ float rh[H];
    int tid = threadIdx.x;
    float rr = 1.f / (1.f + expf(-g_pre[H + tid]));
    rh[tid] = rr * hidden[tid];
    __syncthreads();
    int w = tid >> 5, lane = tid & 31;
    int row = blockIdx.x * 8 + w;
    float s = 0.f;
    for (int k = lane; k < H; k += 32) s += Wh[row * H + k] * rh[k];
    for (int o = 16; o; o >>= 1) s += __shfl_xor_sync(0xffffffffu, s, o);
    if (lane == 0) {
        float c = tanhf(s + g_pre[2 * H + row]);
        float z = 1.f / (1.f + expf(-g_pre[row]));
        hn_out[row] = (1.f - z) * c + z * hidden[row];
    }
}

// ---------------- K8: logits = V_w @ hidden_new + V_b (1024 blocks) -------
__global__ __launch_bounds__(256) void k8_logits(const float* __restrict__ Vw,
                                                 const float* __restrict__ Vb,
                                                 const float* __restrict__ hn) {
    __shared__ float hs[H];
    int tid = threadIdx.x;
    hs[tid] = hn[tid];
    __syncthreads();
    int w = tid >> 5, lane = tid & 31;
    int row = blockIdx.x * 8 + w;
    const float4* v4 = reinterpret_cast<const float4*>(Vw + (size_t)row * H);
    const float4* h4 = reinterpret_cast<const float4*>(hs);
    float4 a = v4[lane], b = h4[lane];
    float s = a.x * b.x + a.y * b.y + a.z * b.z + a.w * b.w;
    a = v4[lane + 32]; b = h4[lane + 32];
    s += a.x * b.x + a.y * b.y + a.z * b.z + a.w * b.w;
    for (int o = 16; o; o >>= 1) s += __shfl_xor_sync(0xffffffffu, s, o);
    if (lane == 0) g_logits[row] = s + Vb[row];
}

// ---------------- K9: log_softmax over V (single block) -------------------
__global__ __launch_bounds__(1024) void k9_lsm(float* __restrict__ out) {
    __shared__ float red[32];
    __shared__ float stat;
    int tid = threadIdx.x;
    float v[8];
    float mx = -1e30f;
#pragma unroll
    for (int i = 0; i < 8; i++) { v[i] = g_logits[i * 1024 + tid]; mx = fmaxf(mx, v[i]); }
    for (int o = 16; o; o >>= 1) mx = fmaxf(mx, __shfl_xor_sync(0xffffffffu, mx, o));
    if ((tid & 31) == 0) red[tid >> 5] = mx;
    __syncthreads();
    if (tid == 0) {
        float m = red[0];
        for (int i = 1; i < 32; i++) m = fmaxf(m, red[i]);
        stat = m;
    }
    __syncthreads();
    mx = stat;
    float sum = 0.f;
#pragma unroll
    for (int i = 0; i < 8; i++) sum += expf(v[i] - mx);
    for (int o = 16; o; o >>= 1) sum += __shfl_xor_sync(0xffffffffu, sum, o);
    __syncthreads();
    if ((tid & 31) == 0) red[tid >> 5] = sum;
    __syncthreads();
    if (tid == 0) {
        float t = 0.f;
        for (int i = 0; i < 32; i++) t += red[i];
        stat = t;
    }
    __syncthreads();
    float lse = mx + logf(stat);
#pragma unroll
    for (int i = 0; i < 8; i++) out[i * 1024 + tid] = v[i] - lse;
}

// ---------------- launch ----------------
extern "C" void kernel_launch(void* const* d_in, const int* in_sizes, int n_in,
                              void* d_out, int out_size) {
    const int*   input_tok = (const int*)d_in[0];
    const float* hidden    = (const float*)d_in[1];
    const float* enc       = (const float*)d_in[2];
    const float* emb       = (const float*)d_in[3];
    const float* Uz_w = (const float*)d_in[4],  *Uz_b = (const float*)d_in[5];
    const float* Wz_w = (const float*)d_in[6],  *Wz_b = (const float*)d_in[7];
    const float* Cz_w = (const float*)d_in[8],  *Cz_b = (const float*)d_in[9];
    const float* Ur_w = (const float*)d_in[10], *Ur_b = (const float*)d_in[11];
    const float* Wr_w = (const float*)d_in[12], *Wr_b = (const float*)d_in[13];
    const float* Cr_w = (const float*)d_in[14], *Cr_b = (const float*)d_in[15];
    const float* Uh_w = (const float*)d_in[16], *Uh_b = (const float*)d_in[17];
    const float* Wh_w = (const float*)d_in[18], *Wh_b = (const float*)d_in[19];
    const float* Ch_w = (const float*)d_in[20], *Ch_b = (const float*)d_in[21];
    const float* Ua_w = (const float*)d_in[22], *Ua_b = (const float*)d_in[23];
    const float* Wa_w = (const float*)d_in[24], *Wa_b = (const float*)d_in[25];
    const float* Va_w = (const float*)d_in[26], *Va_b = (const float*)d_in[27];
    const float* V_w  = (const float*)d_in[28], *V_b  = (const float*)d_in[29];
    (void)Va_b; (void)in_sizes; (void)n_in; (void)out_size;

    float* out = (float*)d_out;           // [0:8192) log-probs
    float* hn  = out + VOCAB;             // [8192:8448) hidden_new
    float* aij = out + VOCAB + H;         // [8448:12544) attention weights

    k2_attn<<<dim3(SEQ / TM, NQ), 128>>>(enc, Ua_w, Va_w, Wa_w, Wa_b, Ua_b, hidden);
    k3_softmax<<<1, 256>>>(aij);
    k4_ci<<<CIB, 512>>>(enc, aij);
    k5_cired<<<8, 512>>>();
    k6_gates<<<768, 512>>>(emb, input_tok, hidden,
                           Uz_w, Uz_b, Wz_w, Wz_b, Cz_w, Cz_b,
                           Ur_w, Ur_b, Wr_w, Wr_b, Cr_w, Cr_b,
                           Uh_w, Uh_b, Wh_b, Ch_w, Ch_b);
    k7_combine<<<32, 256>>>(Wh_w, hidden, hn);
    k8_logits<<<VOCAB / 8, 256>>>(V_w, V_b, hn);
    k9_lsm<<<1, 1024>>>(out);
}

// round 15
// speedup vs baseline: 1.1406x; 1.0462x over previous
#include <cuda_runtime.h>
#include <math.h>

#define H 256
#define H2 512
#define VOCAB 8192
#define SEQ 4096
#define NQ 2               // n-half partial count for Eij

#define CIB 128            // k4 blocks
#define CIR (SEQ / CIB)    // 32 s-rows per block

// ---------------- device scratch (no allocations allowed) ----------------
__device__ float g_Eij[NQ * SEQ];    // attention scores, NQ n-half partials
__device__ float g_CiP[CIB][H2];     // Ci partials (deterministic reduction)
__device__ float g_Ci[H2];           // context vector
__device__ float g_pre[3 * H];       // gate pre-activations: z, r, h-partial
__device__ float g_logits[VOCAB];

// ---------------- f32x2 packed-math helpers (sm_100+) ----------------
static __device__ __forceinline__ unsigned long long pack2(float lo, float hi) {
    unsigned long long r;
    asm("mov.b64 %0, {%1,%2};" : "=l"(r) : "f"(lo), "f"(hi));
    return r;
}
static __device__ __forceinline__ void unpack2(unsigned long long v, float& lo, float& hi) {
    asm("mov.b64 {%0,%1}, %2;" : "=f"(lo), "=f"(hi) : "l"(v));
}
static __device__ __forceinline__ void fma2(unsigned long long& d,
                                            unsigned long long a,
                                            unsigned long long b) {
    asm("fma.rn.f32x2 %0, %1, %2, %0;" : "+l"(d) : "l"(a), "l"(b));
}

// ---------------- K2: fused attention-score GEMM (unchanged) -------------
#define TM 64
#define TN 128
#define KT 32

__global__ __launch_bounds__(128) void k2_attn(const float* __restrict__ enc,
                                               const float* __restrict__ Ua_w,
                                               const float* __restrict__ Va_w,
                                               const float* __restrict__ Wa_w,
                                               const float* __restrict__ Wa_b,
                                               const float* __restrict__ Ua_b,
                                               const float* __restrict__ hidden) {
    __shared__ __align__(16) float As[KT][TM];
    __shared__ __align__(16) float Bs[KT][TN];
    __shared__ float wah_s[TN];
    __shared__ float vas[TN];
    __shared__ __align__(16) float hs[H];

    int tid = threadIdx.x;
    int s0 = blockIdx.x * TM;
    int n0 = blockIdx.y * TN;

    hs[tid] = hidden[tid];
    hs[tid + 128] = hidden[tid + 128];
    vas[tid] = Va_w[n0 + tid];

    int ar = tid >> 1, ac = tid & 1;
    const float4* Ab = reinterpret_cast<const float4*>(enc + (size_t)(s0 + ar) * H2);
    const float4* Bb = reinterpret_cast<const float4*>(Ua_w + (size_t)(n0 + tid) * H2);
    float4 pa[4], pb[8];
#pragma unroll
    for (int q = 0; q < 4; q++) pa[q] = Ab[ac * 4 + q];
#pragma unroll
    for (int q = 0; q < 8; q++) pb[q] = Bb[q];

    __syncthreads();

    {
        int g = n0 + tid;
        const float4* w4 = reinterpret_cast<const float4*>(Wa_w + (size_t)g * H);
        const float4* h4 = reinterpret_cast<const float4*>(hs);
        float r0 = 0.f, r1 = 0.f, r2 = 0.f, r3 = 0.f;
#pragma unroll
        for (int q = 0; q < 64; q += 4) {
            float4 w0 = w4[q + 0], h0 = h4[q + 0];
            float4 w1 = w4[q + 1], h1 = h4[q + 1];
            float4 w2 = w4[q + 2], h2 = h4[q + 2];
            float4 w3 = w4[q + 3], h3 = h4[q + 3];
            r0 += w0.x * h0.x + w0.y * h0.y + w0.z * h0.z + w0.w * h0.w;
            r1 += w1.x * h1.x + w1.y * h1.y + w1.z * h1.z + w1.w * h1.w;
            r2 += w2.x * h2.x + w2.y * h2.y + w2.z * h2.z + w2.w * h2.w;
            r3 += w3.x * h3.x + w3.y * h3.y + w3.z * h3.z + w3.w * h3.w;
        }
        wah_s[tid] = (r0 + r1) + (r2 + r3) + Wa_b[g] + Ua_b[g];
    }

    int tidx = tid & 15;
    int tidy = tid >> 4;

    unsigned long long acc[8][4];
#pragma unroll
    for (int i = 0; i < 8; i++)
#pragma unroll
        for (int j = 0; j < 4; j++) acc[i][j] = 0ull;

    const int NIT = H2 / KT;
    for (int it = 0; it < NIT; ++it) {
#pragma unroll
        for (int q = 0; q < 4; q++) {
            As[ac * 16 + q * 4 + 0][ar] = pa[q].x;
            As[ac * 16 + q * 4 + 1][ar] = pa[q].y;
            As[ac * 16 + q * 4 + 2][ar] = pa[q].z;
            As[ac * 16 + q * 4 + 3][ar] = pa[q].w;
        }
#pragma unroll
        for (int q = 0; q < 8; q++) {
            Bs[q * 4 + 0][tid] = pb[q].x;
            Bs[q * 4 + 1][tid] = pb[q].y;
            Bs[q * 4 + 2][tid] = pb[q].z;
            Bs[q * 4 + 3][tid] = pb[q].w;
        }
        __syncthreads();

        if (it + 1 < NIT) {
            int o = (it + 1) * 8;
#pragma unroll
            for (int q = 0; q < 4; q++) pa[q] = Ab[o + ac * 4 + q];
#pragma unroll
            for (int q = 0; q < 8; q++) pb[q] = Bb[o + q];
        }

#pragma unroll 8
        for (int k = 0; k < KT; k++) {
            float4 af0 = *reinterpret_cast<const float4*>(&As[k][tidy * 8]);
            float4 af1 = *reinterpret_cast<const float4*>(&As[k][tidy * 8 + 4]);
            ulonglong2 b01 = *reinterpret_cast<const ulonglong2*>(&Bs[k][tidx * 8]);
            ulonglong2 b23 = *reinterpret_cast<const ulonglong2*>(&Bs[k][tidx * 8 + 4]);
            unsigned long long a[8], b[4];
            a[0] = pack2(af0.x, af0.x);  a[1] = pack2(af0.y, af0.y);
            a[2] = pack2(af0.z, af0.z);  a[3] = pack2(af0.w, af0.w);
            a[4] = pack2(af1.x, af1.x);  a[5] = pack2(af1.y, af1.y);
            a[6] = pack2(af1.z, af1.z);  a[7] = pack2(af1.w, af1.w);
            b[0] = b01.x; b[1] = b01.y; b[2] = b23.x; b[3] = b23.y;
#pragma unroll
            for (int i = 0; i < 8; i++)
#pragma unroll
                for (int j = 0; j < 4; j++) fma2(acc[i][j], a[i], b[j]);
        }
        __syncthreads();
    }

#pragma unroll
    for (int i = 0; i < 8; i++) {
        float p = 0.f;
#pragma unroll
        for (int j = 0; j < 4; j++) {
            float c0, c1;
            unpack2(acc[i][j], c0, c1);
            int nl = tidx * 8 + 2 * j;
            float e0 = tanhf(c0 + wah_s[nl]);
            float e1 = tanhf(c1 + wah_s[nl + 1]);
            p += e0 * vas[nl] + e1 * vas[nl + 1];
        }
        for (int o = 1; o < 16; o <<= 1) p += __shfl_xor_sync(0xffffffffu, p, o, 16);
        if (tidx == 0) g_Eij[blockIdx.y * SEQ + s0 + tidy * 8 + i] = p;
    }
}

// ---------------- K4: fused softmax + Ci partials + aij (128 blocks) ------
// Each block recomputes the full softmax stats (identical fixed-order
// reduction in every block -> deterministic), writes its 32 aij rows, and
// accumulates its Ci partial.
__global__ __launch_bounds__(512) void k4_ci(const float* __restrict__ enc,
                                             float* __restrict__ aij) {
    __shared__ float red[16];
    __shared__ float stat;
    __shared__ float wsm[CIR];
    int b = blockIdx.x, tid = threadIdx.x;

    cudaGridDependencySynchronize();   // wait for k2's Eij

    // block-local softmax stats over all 4096 scores (8 per thread)
    float e[8];
    float mx = -1e30f;
#pragma unroll
    for (int i = 0; i < 8; i++) {
        int idx = i * 512 + tid;
        e[i] = g_Eij[idx] + g_Eij[SEQ + idx];
        mx = fmaxf(mx, e[i]);
    }
    for (int o = 16; o; o >>= 1) mx = fmaxf(mx, __shfl_xor_sync(0xffffffffu, mx, o));
    if ((tid & 31) == 0) red[tid >> 5] = mx;
    __syncthreads();
    if (tid == 0) {
        float m = red[0];
#pragma unroll
        for (int i = 1; i < 16; i++) m = fmaxf(m, red[i]);
        stat = m;
    }
    __syncthreads();
    float m = stat;

    float sum = 0.f;
#pragma unroll
    for (int i = 0; i < 8; i++) sum += expf(e[i] - m);
    for (int o = 16; o; o >>= 1) sum += __shfl_xor_sync(0xffffffffu, sum, o);
    __syncthreads();
    if ((tid & 31) == 0) red[tid >> 5] = sum;
    __syncthreads();
    if (tid == 0) {
        float t = 0.f;
#pragma unroll
        for (int i = 0; i < 16; i++) t += red[i];
        stat = t;
    }
    __syncthreads();
    float inv = 1.f / stat;

    // this block's 32 attention weights + aij output rows
    if (tid < CIR) {
        float ee = g_Eij[b * CIR + tid] + g_Eij[SEQ + b * CIR + tid];
        float w = expf(ee - m) * inv;
        wsm[tid] = w;
        aij[b * CIR + tid] = w;
    }
    __syncthreads();

    // Ci partial for this block's 32 rows
    const float* ep = enc + (size_t)b * CIR * H2 + tid;
    float acc0 = 0.f, acc1 = 0.f;
#pragma unroll
    for (int s = 0; s < CIR; s += 2) {
        acc0 += wsm[s] * __ldg(ep + (size_t)s * H2);
        acc1 += wsm[s + 1] * __ldg(ep + (size_t)(s + 1) * H2);
    }
    g_CiP[b][tid] = acc0 + acc1;
}

// ---------------- K5: reduce Ci partials (8 blocks, coalesced) ------------
__global__ __launch_bounds__(512) void k5_cired() {
    __shared__ float sm[8][64];
    int tid = threadIdx.x;
    int cl = tid & 63;
    int seg = tid >> 6;
    int col = blockIdx.x * 64 + cl;
    cudaGridDependencySynchronize();   // wait for k4's partials
    float s = 0.f;
#pragma unroll
    for (int r = 0; r < CIB / 8; r++) s += g_CiP[seg * (CIB / 8) + r][col];
    sm[seg][cl] = s;
    __syncthreads();
    if (seg == 0) {
        float t = 0.f;
#pragma unroll
        for (int i = 0; i < 8; i++) t += sm[i][cl];
        g_Ci[col] = t;
    }
}

// ---------------- K6: gate pre-activations (768 blocks x 512 thr) --------
// The big U.y mainloop is independent of attention -> runs concurrently with
// k4/k5 under PDL; only the Ci term waits.
__global__ __launch_bounds__(512) void k6_gates(
    const float* __restrict__ emb, const int* __restrict__ tokp,
    const float* __restrict__ hidden,
    const float* __restrict__ Uz, const float* __restrict__ Uzb,
    const float* __restrict__ Wz, const float* __restrict__ Wzb,
    const float* __restrict__ Cz, const float* __restrict__ Czb,
    const float* __restrict__ Ur, const float* __restrict__ Urb,
    const float* __restrict__ Wr, const float* __restrict__ Wrb,
    const float* __restrict__ Cr, const float* __restrict__ Crb,
    const float* __restrict__ Uh, const float* __restrict__ Uhb,
    const float* __restrict__ Whb,
    const float* __restrict__ Ch, const float* __restrict__ Chb) {
    __shared__ float red[16];
    int g = blockIdx.x >> 8, row = blockIdx.x & 255, tid = threadIdx.x;
    const float* U = (g == 0) ? Uz : (g == 1) ? Ur : Uh;
    int tok = __ldg(tokp);
    const float4* y4 = reinterpret_cast<const float4*>(emb + (size_t)tok * VOCAB);
    const float4* u4 = reinterpret_cast<const float4*>(U + (size_t)row * VOCAB);

    float s = 0.f;
#pragma unroll
    for (int q = 0; q < 4; q++) {
        int i = tid + q * 512;
        float4 u = u4[i], y = y4[i];
        s += u.x * y.x + u.y * y.y + u.z * y.z + u.w * y.w;
    }

    cudaGridDependencySynchronize();   // g_Ci now needed

    if (tid < 256) {
        if (g < 2) {
            const float* W = (g == 0) ? Wz : Wr;
            s += W[row * H + tid] * hidden[tid];
        }
        const float* C = (g == 0) ? Cz : (g == 1) ? Cr : Ch;
        s += C[row * H2 + tid] * g_Ci[tid] + C[row * H2 + tid + 256] * g_Ci[tid + 256];
    }

    for (int o = 16; o; o >>= 1) s += __shfl_xor_sync(0xffffffffu, s, o);
    if ((tid & 31) == 0) red[tid >> 5] = s;
    __syncthreads();
    if (tid == 0) {
        float t = 0.f;
#pragma unroll
        for (int i = 0; i < 16; i++) t += red[i];
        float bias = (g == 0) ? (Uzb[row] + Wzb[row] + Czb[row])
                   : (g == 1) ? (Urb[row] + Wrb[row] + Crb[row])
                              : (Uhb[row] + Whb[row] + Chb[row]);
        g_pre[g * H + row] = t + bias;
    }
}

// ---------------- K7: finish GRU -> hidden_new (32 blocks) ----------------
__global__ __launch_bounds__(256) void k7_combine(const float* __restrict__ Wh,
                                                  const float* __restrict__ hidden,
                                                  float* __restrict__ hn_out) {
    __shared__ float rh[H];
    int tid = threadIdx.x;
    int w = tid >> 5, lane = tid & 31;
    int row = blockIdx.x * 8 + w;
    // prefetch Wh row chunk (independent of k6)
    float wreg[8];
#pragma unroll
    for (int k = 0; k < 8; k++) wreg[k] = Wh[row * H + lane + 32 * k];

    cudaGridDependencySynchronize();   // g_pre ready

    float rr = 1.f / (1.f + expf(-g_pre[H + tid]));
    rh[tid] = rr * hidden[tid];
    __syncthreads();
    float s = 0.f;
#pragma unroll
    for (int k = 0; k < 8; k++) s += wreg[k] * rh[lane + 32 * k];
    for (int o = 16; o; o >>= 1) s += __shfl_xor_sync(0xffffffffu, s, o);
    if (lane == 0) {
        float c = tanhf(s + g_pre[2 * H + row]);
        float z = 1.f / (1.f + expf(-g_pre[row]));
        hn_out[row] = (1.f - z) * c + z * hidden[row];
    }
}

// ---------------- K8: logits = V_w @ hidden_new + V_b (1024 blocks) -------
__global__ __launch_bounds__(256) void k8_logits(const float* __restrict__ Vw,
                                                 const float* __restrict__ Vb,
                                                 const float* __restrict__ hn) {
    __shared__ float hs[H];
    int tid = threadIdx.x;
    int w = tid >> 5, lane = tid & 31;
    int row = blockIdx.x * 8 + w;
    const float4* v4 = reinterpret_cast<const float4*>(Vw + (size_t)row * H);
    // prefetch V_w rows (independent of k7)
    float4 a0 = v4[lane], a1 = v4[lane + 32];
    float bias = (lane == 0) ? Vb[row] : 0.f;

    cudaGridDependencySynchronize();   // hn ready

    hs[tid] = hn[tid];
    __syncthreads();
    const float4* h4 = reinterpret_cast<const float4*>(hs);
    float4 b0 = h4[lane], b1 = h4[lane + 32];
    float s = a0.x * b0.x + a0.y * b0.y + a0.z * b0.z + a0.w * b0.w
            + a1.x * b1.x + a1.y * b1.y + a1.z * b1.z + a1.w * b1.w;
    for (int o = 16; o; o >>= 1) s += __shfl_xor_sync(0xffffffffu, s, o);
    if (lane == 0) g_logits[row] = s + bias;
}

// ---------------- K9: log_softmax over V (single block) -------------------
__global__ __launch_bounds__(1024) void k9_lsm(float* __restrict__ out) {
    __shared__ float red[32];
    __shared__ float stat;
    int tid = threadIdx.x;
    cudaGridDependencySynchronize();   // logits ready
    float v[8];
    float mx = -1e30f;
#pragma unroll
    for (int i = 0; i < 8; i++) { v[i] = g_logits[i * 1024 + tid]; mx = fmaxf(mx, v[i]); }
    for (int o = 16; o; o >>= 1) mx = fmaxf(mx, __shfl_xor_sync(0xffffffffu, mx, o));
    if ((tid & 31) == 0) red[tid >> 5] = mx;
    __syncthreads();
    if (tid == 0) {
        float m = red[0];
        for (int i = 1; i < 32; i++) m = fmaxf(m, red[i]);
        stat = m;
    }
    __syncthreads();
    mx = stat;
    float sum = 0.f;
#pragma unroll
    for (int i = 0; i < 8; i++) sum += expf(v[i] - mx);
    for (int o = 16; o; o >>= 1) sum += __shfl_xor_sync(0xffffffffu, sum, o);
    __syncthreads();
    if ((tid & 31) == 0) red[tid >> 5] = sum;
    __syncthreads();
    if (tid == 0) {
        float t = 0.f;
        for (int i = 0; i < 32; i++) t += red[i];
        stat = t;
    }
    __syncthreads();
    float lse = mx + logf(stat);
#pragma unroll
    for (int i = 0; i < 8; i++) out[i * 1024 + tid] = v[i] - lse;
}

// ---------------- launch (PDL on all dependent kernels) -------------------
template <typename F, typename... Args>
static inline void pdl_launch(F f, dim3 grid, dim3 block, Args... args) {
    cudaLaunchAttribute attr[1];
    attr[0].id = cudaLaunchAttributeProgrammaticStreamSerialization;
    attr[0].val.programmaticStreamSerializationAllowed = 1;
    cudaLaunchConfig_t cfg = {};
    cfg.gridDim = grid;
    cfg.blockDim = block;
    cfg.dynamicSmemBytes = 0;
    cfg.stream = 0;
    cfg.attrs = attr;
    cfg.numAttrs = 1;
    cudaLaunchKernelEx(&cfg, f, args...);
}

extern "C" void kernel_launch(void* const* d_in, const int* in_sizes, int n_in,
                              void* d_out, int out_size) {
    const int*   input_tok = (const int*)d_in[0];
    const float* hidden    = (const float*)d_in[1];
    const float* enc       = (const float*)d_in[2];
    const float* emb       = (const float*)d_in[3];
    const float* Uz_w = (const float*)d_in[4],  *Uz_b = (const float*)d_in[5];
    const float* Wz_w = (const float*)d_in[6],  *Wz_b = (const float*)d_in[7];
    const float* Cz_w = (const float*)d_in[8],  *Cz_b = (const float*)d_in[9];
    const float* Ur_w = (const float*)d_in[10], *Ur_b = (const float*)d_in[11];
    const float* Wr_w = (const float*)d_in[12], *Wr_b = (const float*)d_in[13];
    const float* Cr_w = (const float*)d_in[14], *Cr_b = (const float*)d_in[15];
    const float* Uh_w = (const float*)d_in[16], *Uh_b = (const float*)d_in[17];
    const float* Wh_w = (const float*)d_in[18], *Wh_b = (const float*)d_in[19];
    const float* Ch_w = (const float*)d_in[20], *Ch_b = (const float*)d_in[21];
    const float* Ua_w = (const float*)d_in[22], *Ua_b = (const float*)d_in[23];
    const float* Wa_w = (const float*)d_in[24], *Wa_b = (const float*)d_in[25];
    const float* Va_w = (const float*)d_in[26], *Va_b = (const float*)d_in[27];
    const float* V_w  = (const float*)d_in[28], *V_b  = (const float*)d_in[29];
    (void)Va_b; (void)in_sizes; (void)n_in; (void)out_size;

    float* out = (float*)d_out;           // [0:8192) log-probs
    float* hn  = out + VOCAB;             // [8192:8448) hidden_new
    float* aij = out + VOCAB + H;         // [8448:12544) attention weights

    k2_attn<<<dim3(SEQ / TM, NQ), 128>>>(enc, Ua_w, Va_w, Wa_w, Wa_b, Ua_b, hidden);
    pdl_launch(k4_ci, dim3(CIB), dim3(512), enc, aij);
    pdl_launch(k5_cired, dim3(8), dim3(512));
    pdl_launch(k6_gates, dim3(768), dim3(512), emb, input_tok, hidden,
               Uz_w, Uz_b, Wz_w, Wz_b, Cz_w, Cz_b,
               Ur_w, Ur_b, Wr_w, Wr_b, Cr_w, Cr_b,
               Uh_w, Uh_b, Wh_b, Ch_w, Ch_b);
    pdl_launch(k7_combine, dim3(32), dim3(256), Wh_w, hidden, hn);
    pdl_launch(k8_logits, dim3(VOCAB / 8), dim3(256), V_w, V_b, hn);
    pdl_launch(k9_lsm, dim3(1), dim3(1024), out);
}